// round 11
// baseline (speedup 1.0000x reference)
#include <cuda_runtime.h>
#include <cuda_bf16.h>
#include <cstdint>

// AddingGaussianBlur: x (64,512,512,3) f32, stds (64,) f32 -> out f32.
//
// Separable (reference's 3x3 kernel depends only on column index):
//   out = inv * sum_{3 rows} h(row),  h[e] = a*(x[e-3]+x[e+3]) + x[e]
//   a = exp(-1/s^2), s = 3*std[b], inv = 1/(3*(1+2a))
//
// R11 = R10 (horizontal-first: cp.async.cg row ring, 3 LDS.128/row straight
// from the ring, hm/hc/hp rolling in registers, 1 barrier/row placed right
// after wait_group) with the ring shrunk 8 -> 4 slots (49KB -> 25KB smem).
// At 32 regs / 25KB smem / 384 thr, 5 blocks/SM co-reside NATURALLY (no
// launch-bounds squeeze -> codegen untouched): 60 warps, 93.75% theoretical
// occupancy. 2 rows in flight per block x 5 blocks = ~60KB/SM in-flight.

#define H       512
#define ROWW    1536            // 512 * 3 floats per image row
#define NT      384             // one thread per float4 chunk
#define RPB     32              // rows per block band
#define NSLOT   4               // ring slots (power of 2) -> 24KB ring

__global__ __launch_bounds__(NT)
void gauss_blur_kernel(const float* __restrict__ x,
                       const float* __restrict__ stds,
                       float* __restrict__ out)
{
    __shared__ __align__(16) float ring[NSLOT][ROWW];

    const int b  = blockIdx.y;
    const int i0 = blockIdx.x * RPB;
    const int t  = threadIdx.x;

    const float s   = stds[b] * 3.0f;
    const float a   = expf(-1.0f / (s * s));
    const float inv = 1.0f / (3.0f * (1.0f + 2.0f * a));

    const float* __restrict__ xb = x   + (size_t)b * H * ROWW;
    float*       __restrict__ ob = out + (size_t)b * H * ROWW;

    const uint32_t ring_smem = (uint32_t)__cvta_generic_to_shared(&ring[0][0]) + t * 16u;
    const float4 Z = make_float4(0.0f, 0.0f, 0.0f, 0.0f);
    const bool hasL = (t > 0);
    const bool hasR = (t < NT - 1);

    // Issue one row into ring slot (gi - i0 + 1) & 3. cp.async.cg when in
    // range, STS zeros otherwise; always commits a group (static wait counts).
    auto issue = [&](int gi) {
        const int slot = (gi - i0 + 1) & (NSLOT - 1);
        if ((unsigned)gi < (unsigned)H) {
            const float* src = xb + (size_t)gi * ROWW + t * 4;
            const uint32_t dst = ring_smem + slot * (ROWW * 4);
            asm volatile("cp.async.cg.shared.global [%0], [%1], 16;\n"
                         :: "r"(dst), "l"(src));
        } else {
            reinterpret_cast<float4*>(ring[slot] + t * 4)[0] = Z;
        }
        asm volatile("cp.async.commit_group;\n");
    };

    // Horizontal pass on the row in `slot`: h[e] = a*(x[e-3]+x[e+3]) + x[e].
    auto hrow = [&](int slot) -> float4 {
        const float4* rp4 = reinterpret_cast<const float4*>(ring[slot]);
        const float4 C = rp4[t];
        const float4 L = hasL ? rp4[t - 1] : Z;
        const float4 R = hasR ? rp4[t + 1] : Z;
        float4 h;
        h.x = fmaf(a, L.y + C.w, C.x);
        h.y = fmaf(a, L.z + R.x, C.y);
        h.z = fmaf(a, L.w + R.y, C.z);
        h.w = fmaf(a, C.x + R.z, C.w);
        return h;
    };

    // Prologue: rows i0-1 .. i0+2 (4 groups); wait until rows i0-1, i0 have
    // landed (2 pending), fence, build hm/hc.
    issue(i0 - 1); issue(i0); issue(i0 + 1); issue(i0 + 2);
    asm volatile("cp.async.wait_group 2;\n");
    __syncthreads();

    float4 hm = hrow(0);   // h(row i0-1)
    float4 hc = hrow(1);   // h(row i0)

    #pragma unroll 1
    for (int r = 0; r < RPB; r++) {
        const int gi = i0 + r;

        // row gi+1 complete (1 group pending: gi+2), then cross-thread fence
        asm volatile("cp.async.wait_group 1;\n");
        __syncthreads();

        const float4 hp = hrow((r + 2) & (NSLOT - 1));   // h(row gi+1)

        float4 o;
        o.x = inv * (hm.x + hc.x + hp.x);
        o.y = inv * (hm.y + hc.y + hp.y);
        o.z = inv * (hm.z + hc.z + hp.z);
        o.w = inv * (hm.w + hc.w + hp.w);

        __stcs(&reinterpret_cast<float4*>(ob + (size_t)gi * ROWW)[t], o);

        // refill AFTER the barrier: slot of row gi+3 was last read at
        // iteration r-2, separated from this write by two barriers.
        issue(gi + 3);

        hm = hc; hc = hp;
    }
}

extern "C" void kernel_launch(void* const* d_in, const int* in_sizes, int n_in,
                              void* d_out, int out_size)
{
    const float* x    = (const float*)d_in[0];
    const float* stds = (const float*)d_in[1];
    float* out        = (float*)d_out;

    dim3 grid(H / RPB, 64);   // (16, 64) = 1024 blocks
    gauss_blur_kernel<<<grid, NT>>>(x, stds, out);
}

// round 12
// speedup vs baseline: 1.0552x; 1.0552x over previous
#include <cuda_runtime.h>
#include <cuda_bf16.h>
#include <cstdint>

// AddingGaussianBlur: x (64,512,512,3) f32, stds (64,) f32 -> out f32.
//
// Separable (reference's 3x3 kernel depends only on column index):
//   out = inv * sum_{3 rows} h(row),  h[e] = a*(x[e-3]+x[e+3]) + x[e]
//   a = exp(-1/s^2), s = 3*std[b], inv = 1/(3*(1+2a))
//
// R12 = R10 (horizontal-first cp.async.cg row ring, 3 LDS.128/row from the
// ring, hm/hc/hp rolling in registers, 1 barrier/row right after wait_group)
// with a 6-slot ring (36KB smem):
//   - 5 blocks/SM co-reside (vs 4 at R10's 48KB ring): 60 warps
//   - 3 pending cp.async groups at the wait (R10 had 5, R11's failing 1)
// Depth x occupancy: 5 blocks x 3 rows x 6KB = 90KB/SM in flight.
// Mod-6 slot indices maintained incrementally (no power-of-2 needed).

#define H       512
#define ROWW    1536            // 512 * 3 floats per image row
#define NT      384             // one thread per float4 chunk
#define RPB     32              // rows per block band
#define NSLOT   6               // ring slots -> 36KB ring

__global__ __launch_bounds__(NT)
void gauss_blur_kernel(const float* __restrict__ x,
                       const float* __restrict__ stds,
                       float* __restrict__ out)
{
    __shared__ __align__(16) float ring[NSLOT][ROWW];

    const int b  = blockIdx.y;
    const int i0 = blockIdx.x * RPB;
    const int t  = threadIdx.x;

    const float s   = stds[b] * 3.0f;
    const float a   = expf(-1.0f / (s * s));
    const float inv = 1.0f / (3.0f * (1.0f + 2.0f * a));

    const float* __restrict__ xb = x   + (size_t)b * H * ROWW;
    float*       __restrict__ ob = out + (size_t)b * H * ROWW;

    const uint32_t ring_smem = (uint32_t)__cvta_generic_to_shared(&ring[0][0]) + t * 16u;
    const float4 Z = make_float4(0.0f, 0.0f, 0.0f, 0.0f);
    const bool hasL = (t > 0);
    const bool hasR = (t < NT - 1);

    // Issue one row into the given ring slot. cp.async.cg when in range,
    // STS zeros otherwise; always commits a group (static wait counts).
    auto issue = [&](int gi, int slot) {
        if ((unsigned)gi < (unsigned)H) {
            const float* src = xb + (size_t)gi * ROWW + t * 4;
            const uint32_t dst = ring_smem + slot * (ROWW * 4);
            asm volatile("cp.async.cg.shared.global [%0], [%1], 16;\n"
                         :: "r"(dst), "l"(src));
        } else {
            reinterpret_cast<float4*>(ring[slot] + t * 4)[0] = Z;
        }
        asm volatile("cp.async.commit_group;\n");
    };

    // Horizontal pass on the row in `slot`: h[e] = a*(x[e-3]+x[e+3]) + x[e].
    auto hrow = [&](int slot) -> float4 {
        const float4* rp4 = reinterpret_cast<const float4*>(ring[slot]);
        const float4 C = rp4[t];
        const float4 L = hasL ? rp4[t - 1] : Z;
        const float4 R = hasR ? rp4[t + 1] : Z;
        float4 h;
        h.x = fmaf(a, L.y + C.w, C.x);
        h.y = fmaf(a, L.z + R.x, C.y);
        h.z = fmaf(a, L.w + R.y, C.z);
        h.w = fmaf(a, C.x + R.z, C.w);
        return h;
    };

    // Prologue: rows i0-1 .. i0+4 into slots 0..5 (6 groups); wait until
    // rows i0-1, i0 landed (4 pending), fence, build hm/hc.
    issue(i0 - 1, 0); issue(i0,     1); issue(i0 + 1, 2);
    issue(i0 + 2, 3); issue(i0 + 3, 4); issue(i0 + 4, 5);
    asm volatile("cp.async.wait_group 4;\n");
    __syncthreads();

    float4 hm = hrow(0);   // h(row i0-1)
    float4 hc = hrow(1);   // h(row i0)

    int sl_rd = 2;   // slot of row gi+1 at iteration r   ((r+2) mod 6)
    int sl_wr = 0;   // slot for row gi+5 at iteration r  ((r+6) mod 6 = r mod 6)

    #pragma unroll 1
    for (int r = 0; r < RPB; r++) {
        const int gi = i0 + r;

        // row gi+1 complete (3 groups pending: gi+2..gi+4), then fence
        asm volatile("cp.async.wait_group 3;\n");
        __syncthreads();

        const float4 hp = hrow(sl_rd);   // h(row gi+1)

        float4 o;
        o.x = inv * (hm.x + hc.x + hp.x);
        o.y = inv * (hm.y + hc.y + hp.y);
        o.z = inv * (hm.z + hc.z + hp.z);
        o.w = inv * (hm.w + hc.w + hp.w);

        __stcs(&reinterpret_cast<float4*>(ob + (size_t)gi * ROWW)[t], o);

        // refill AFTER the barrier: slot sl_wr held row gi-1, last read at
        // iteration r-2 -> two barriers separate that read from this write.
        issue(gi + 5, sl_wr);

        hm = hc; hc = hp;
        sl_rd = (sl_rd + 1 == NSLOT) ? 0 : sl_rd + 1;
        sl_wr = (sl_wr + 1 == NSLOT) ? 0 : sl_wr + 1;
    }
}

extern "C" void kernel_launch(void* const* d_in, const int* in_sizes, int n_in,
                              void* d_out, int out_size)
{
    const float* x    = (const float*)d_in[0];
    const float* stds = (const float*)d_in[1];
    float* out        = (float*)d_out;

    dim3 grid(H / RPB, 64);   // (16, 64) = 1024 blocks
    gauss_blur_kernel<<<grid, NT>>>(x, stds, out);
}

// round 13
// speedup vs baseline: 1.1174x; 1.0589x over previous
#include <cuda_runtime.h>
#include <cuda_bf16.h>
#include <cstdint>

// AddingGaussianBlur: x (64,512,512,3) f32, stds (64,) f32 -> out f32.
//
// Separable (reference's 3x3 kernel depends only on column index):
//   out = inv * sum_{3 rows} h(row),  h[e] = a*(x[e-3]+x[e+3]) + x[e]
//   a = exp(-1/s^2), s = 3*std[b], inv = 1/(3*(1+2a))
//
// R13 = R12 (horizontal-first cp.async.cg 6-slot ring, 3 LDS.128/row,
// hm/hc/hp rolling in registers, 1 barrier/row, 5 blocks/SM) with RPB 32->16:
// grid 1024 -> 2048 blocks vs 740 concurrent, so the wave-quantization
// critical path drops from 2x66 to 3x34 traffic-units (-23%) for +3% total
// traffic. Issues past the band end become empty commit_groups so the static
// wait_group counts hold without reading the next band's rows.

#define H       512
#define ROWW    1536            // 512 * 3 floats per image row
#define NT      384             // one thread per float4 chunk
#define RPB     16              // rows per block band
#define NSLOT   6               // ring slots -> 36KB ring

__global__ __launch_bounds__(NT)
void gauss_blur_kernel(const float* __restrict__ x,
                       const float* __restrict__ stds,
                       float* __restrict__ out)
{
    __shared__ __align__(16) float ring[NSLOT][ROWW];

    const int b  = blockIdx.y;
    const int i0 = blockIdx.x * RPB;
    const int t  = threadIdx.x;

    const float s   = stds[b] * 3.0f;
    const float a   = expf(-1.0f / (s * s));
    const float inv = 1.0f / (3.0f * (1.0f + 2.0f * a));

    const float* __restrict__ xb = x   + (size_t)b * H * ROWW;
    float*       __restrict__ ob = out + (size_t)b * H * ROWW;

    const uint32_t ring_smem = (uint32_t)__cvta_generic_to_shared(&ring[0][0]) + t * 16u;
    const float4 Z = make_float4(0.0f, 0.0f, 0.0f, 0.0f);
    const bool hasL = (t > 0);
    const bool hasR = (t < NT - 1);
    const int  iend = i0 + RPB;       // last row this band ever reads

    // Issue one row into the given ring slot. Real cp.async.cg only for rows
    // this band actually consumes (gi <= iend); zeros when out of the image;
    // otherwise just commit an empty group (keeps wait counts static).
    auto issue = [&](int gi, int slot) {
        if (gi <= iend) {
            if ((unsigned)gi < (unsigned)H) {
                const float* src = xb + (size_t)gi * ROWW + t * 4;
                const uint32_t dst = ring_smem + slot * (ROWW * 4);
                asm volatile("cp.async.cg.shared.global [%0], [%1], 16;\n"
                             :: "r"(dst), "l"(src));
            } else {
                reinterpret_cast<float4*>(ring[slot] + t * 4)[0] = Z;
            }
        }
        asm volatile("cp.async.commit_group;\n");
    };

    // Horizontal pass on the row in `slot`: h[e] = a*(x[e-3]+x[e+3]) + x[e].
    auto hrow = [&](int slot) -> float4 {
        const float4* rp4 = reinterpret_cast<const float4*>(ring[slot]);
        const float4 C = rp4[t];
        const float4 L = hasL ? rp4[t - 1] : Z;
        const float4 R = hasR ? rp4[t + 1] : Z;
        float4 h;
        h.x = fmaf(a, L.y + C.w, C.x);
        h.y = fmaf(a, L.z + R.x, C.y);
        h.z = fmaf(a, L.w + R.y, C.z);
        h.w = fmaf(a, C.x + R.z, C.w);
        return h;
    };

    // Prologue: rows i0-1 .. i0+4 into slots 0..5 (6 groups); wait until
    // rows i0-1, i0 landed (4 pending), fence, build hm/hc.
    issue(i0 - 1, 0); issue(i0,     1); issue(i0 + 1, 2);
    issue(i0 + 2, 3); issue(i0 + 3, 4); issue(i0 + 4, 5);
    asm volatile("cp.async.wait_group 4;\n");
    __syncthreads();

    float4 hm = hrow(0);   // h(row i0-1)
    float4 hc = hrow(1);   // h(row i0)

    int sl_rd = 2;   // slot of row gi+1 at iteration r   ((r+2) mod 6)
    int sl_wr = 0;   // slot for row gi+5 at iteration r  ((r+6) mod 6 = r mod 6)

    #pragma unroll 1
    for (int r = 0; r < RPB; r++) {
        const int gi = i0 + r;

        // row gi+1's group complete (3 groups pending), then fence
        asm volatile("cp.async.wait_group 3;\n");
        __syncthreads();

        const float4 hp = hrow(sl_rd);   // h(row gi+1)

        float4 o;
        o.x = inv * (hm.x + hc.x + hp.x);
        o.y = inv * (hm.y + hc.y + hp.y);
        o.z = inv * (hm.z + hc.z + hp.z);
        o.w = inv * (hm.w + hc.w + hp.w);

        __stcs(&reinterpret_cast<float4*>(ob + (size_t)gi * ROWW)[t], o);

        // refill AFTER the barrier: slot sl_wr held row gi-1, last read at
        // iteration r-2 -> two barriers separate that read from this write.
        issue(gi + 5, sl_wr);

        hm = hc; hc = hp;
        sl_rd = (sl_rd + 1 == NSLOT) ? 0 : sl_rd + 1;
        sl_wr = (sl_wr + 1 == NSLOT) ? 0 : sl_wr + 1;
    }
}

extern "C" void kernel_launch(void* const* d_in, const int* in_sizes, int n_in,
                              void* d_out, int out_size)
{
    const float* x    = (const float*)d_in[0];
    const float* stds = (const float*)d_in[1];
    float* out        = (float*)d_out;

    dim3 grid(H / RPB, 64);   // (32, 64) = 2048 blocks
    gauss_blur_kernel<<<grid, NT>>>(x, stds, out);
}

// round 14
// speedup vs baseline: 1.1216x; 1.0038x over previous
#include <cuda_runtime.h>
#include <cuda_bf16.h>
#include <cstdint>

// AddingGaussianBlur: x (64,512,512,3) f32, stds (64,) f32 -> out f32.
//
// Separable (reference's 3x3 kernel depends only on column index):
//   out = inv * sum_{3 rows} h(row),  h[e] = a*(x[e-3]+x[e+3]) + x[e]
//   a = exp(-1/s^2), s = 3*std[b], inv = 1/(3*(1+2a))
//
// R14 = R13 (horizontal-first cp.async.cg ring, 3 LDS.128/row, hm/hc/hp in
// registers, 1 barrier/row, RPB=16 for the wave tail) with:
//   - NSLOT 6 -> 7 (42KB static smem, still 5 blocks/SM): pending depth at
//     the wait rises 3 -> 5, the depth that won in R10, now at R13 occupancy
//   - issue hoisted ABOVE wait_group: the next row's copy starts one
//     compute-phase earlier (WAR-safe: one barrier separates the slot's
//     last read from the rewrite)

#define H       512
#define ROWW    1536            // 512 * 3 floats per image row
#define NT      384             // one thread per float4 chunk
#define RPB     16              // rows per block band
#define NSLOT   7               // ring slots -> 42KB ring

__global__ __launch_bounds__(NT)
void gauss_blur_kernel(const float* __restrict__ x,
                       const float* __restrict__ stds,
                       float* __restrict__ out)
{
    __shared__ __align__(16) float ring[NSLOT][ROWW];

    const int b  = blockIdx.y;
    const int i0 = blockIdx.x * RPB;
    const int t  = threadIdx.x;

    const float s   = stds[b] * 3.0f;
    const float a   = expf(-1.0f / (s * s));
    const float inv = 1.0f / (3.0f * (1.0f + 2.0f * a));

    const float* __restrict__ xb = x   + (size_t)b * H * ROWW;
    float*       __restrict__ ob = out + (size_t)b * H * ROWW;

    const uint32_t ring_smem = (uint32_t)__cvta_generic_to_shared(&ring[0][0]) + t * 16u;
    const float4 Z = make_float4(0.0f, 0.0f, 0.0f, 0.0f);
    const bool hasL = (t > 0);
    const bool hasR = (t < NT - 1);
    const int  iend = i0 + RPB;       // last row this band ever reads

    // Issue one row into the given ring slot. Real cp.async.cg only for rows
    // this band consumes (gi <= iend); zeros when outside the image;
    // otherwise just an empty commit_group (keeps wait counts static).
    auto issue = [&](int gi, int slot) {
        if (gi <= iend) {
            if ((unsigned)gi < (unsigned)H) {
                const float* src = xb + (size_t)gi * ROWW + t * 4;
                const uint32_t dst = ring_smem + slot * (ROWW * 4);
                asm volatile("cp.async.cg.shared.global [%0], [%1], 16;\n"
                             :: "r"(dst), "l"(src));
            } else {
                reinterpret_cast<float4*>(ring[slot] + t * 4)[0] = Z;
            }
        }
        asm volatile("cp.async.commit_group;\n");
    };

    // Horizontal pass on the row in `slot`: h[e] = a*(x[e-3]+x[e+3]) + x[e].
    auto hrow = [&](int slot) -> float4 {
        const float4* rp4 = reinterpret_cast<const float4*>(ring[slot]);
        const float4 C = rp4[t];
        const float4 L = hasL ? rp4[t - 1] : Z;
        const float4 R = hasR ? rp4[t + 1] : Z;
        float4 h;
        h.x = fmaf(a, L.y + C.w, C.x);
        h.y = fmaf(a, L.z + R.x, C.y);
        h.z = fmaf(a, L.w + R.y, C.z);
        h.w = fmaf(a, C.x + R.z, C.w);
        return h;
    };

    // Prologue: rows i0-1 .. i0+5 into slots 0..6 (7 groups); wait until
    // rows i0-1, i0 landed (5 pending), fence, build hm/hc.
    issue(i0 - 1, 0); issue(i0,     1); issue(i0 + 1, 2); issue(i0 + 2, 3);
    issue(i0 + 3, 4); issue(i0 + 4, 5); issue(i0 + 5, 6);
    asm volatile("cp.async.wait_group 5;\n");
    __syncthreads();

    float4 hm = hrow(0);   // h(row i0-1)
    float4 hc = hrow(1);   // h(row i0)

    int sl_rd = 2;   // slot of row gi+1 at iteration r   ((r+2) mod 7)
    int sl_wr = 0;   // slot for row gi+6 at iteration r  ((r+7) mod 7 = r mod 7)

    #pragma unroll 1
    for (int r = 0; r < RPB; r++) {
        const int gi = i0 + r;

        // Issue row gi+6 BEFORE waiting: slot sl_wr held row gi-1, last read
        // at iteration r-2; barrier r-1 separates that read from this write.
        issue(gi + 6, sl_wr);

        // row gi+1's group complete (<=5 groups pending), then fence
        asm volatile("cp.async.wait_group 5;\n");
        __syncthreads();

        const float4 hp = hrow(sl_rd);   // h(row gi+1)

        float4 o;
        o.x = inv * (hm.x + hc.x + hp.x);
        o.y = inv * (hm.y + hc.y + hp.y);
        o.z = inv * (hm.z + hc.z + hp.z);
        o.w = inv * (hm.w + hc.w + hp.w);

        __stcs(&reinterpret_cast<float4*>(ob + (size_t)gi * ROWW)[t], o);

        hm = hc; hc = hp;
        sl_rd = (sl_rd + 1 == NSLOT) ? 0 : sl_rd + 1;
        sl_wr = (sl_wr + 1 == NSLOT) ? 0 : sl_wr + 1;
    }
}

extern "C" void kernel_launch(void* const* d_in, const int* in_sizes, int n_in,
                              void* d_out, int out_size)
{
    const float* x    = (const float*)d_in[0];
    const float* stds = (const float*)d_in[1];
    float* out        = (float*)d_out;

    dim3 grid(H / RPB, 64);   // (32, 64) = 2048 blocks
    gauss_blur_kernel<<<grid, NT>>>(x, stds, out);
}